// round 1
// baseline (speedup 1.0000x reference)
#include <cuda_runtime.h>
#include <math.h>

// Problem constants
#define RB      64      // rows per CTA
#define NT      256     // threads per CTA
#define HD      256     // hidden dim
#define OUTC    184     // output cols (8 * 23)
#define OUTP    192     // padded output cols
#define KT      32      // k-panel size
#define NBINS   8
#define TRANS   8

// Dynamic smem layout (floats):
//   h0s : [0      , 16384)   64x256  (reused for raw 64x192 later)
//   h1s : [16384  , 32768)   64x256
//   Ws  : [32768  , 40960)   32x256 panel (GEMM2 uses 32x192 of it)
//   x2s : [40960  , 41472)   64x8
//   lds : [41472  , 41536)   64
#define SMEM_FLOATS 41536

__device__ __forceinline__ float softplusf(float v) {
    return fmaxf(v, 0.0f) + log1pf(expf(-fabsf(v)));
}

__global__ void __launch_bounds__(NT, 1)
coupling_spline_kernel(const float* __restrict__ x,
                       const float* __restrict__ W0,
                       const float* __restrict__ b0,
                       const float* __restrict__ W1,
                       const float* __restrict__ b1,
                       const float* __restrict__ Wout,
                       const float* __restrict__ bout,
                       float* __restrict__ out,
                       int B)
{
    extern __shared__ float smem[];
    float* h0s = smem;                 // 64x256 ; later raw 64x192
    float* h1s = smem + 16384;         // 64x256
    float* Ws  = smem + 32768;         // panel
    float* x2s = smem + 40960;         // 64x8
    float* lds = smem + 41472;         // 64

    const int tid  = threadIdx.x;
    const int row0 = blockIdx.x * RB;
    const int tx = tid & 31;
    const int ty = tid >> 5;

    // ---- load x2 tile, init logdet accum ----
    for (int e = tid; e < RB * 8; e += NT) {
        int r = e >> 3, j = e & 7;
        x2s[e] = x[(size_t)(row0 + r) * 16 + 8 + j];
    }
    if (tid < RB) lds[tid] = 0.0f;
    __syncthreads();

    // ---- stage 1: h0 = relu(x2 @ W0 + b0), col = tid ----
    {
        float w0c[8];
        #pragma unroll
        for (int j = 0; j < 8; j++) w0c[j] = W0[j * HD + tid];
        const float bb = b0[tid];
        for (int r = 0; r < RB; r++) {
            float s = bb;
            #pragma unroll
            for (int j = 0; j < 8; j++) s = fmaf(x2s[r * 8 + j], w0c[j], s);
            h0s[r * HD + tid] = fmaxf(s, 0.0f);
        }
    }
    __syncthreads();

    // ---- stage 2: h1 = relu(h0 @ W1 + b1), 8x8 register tile ----
    {
        float acc[8][8];
        #pragma unroll
        for (int i = 0; i < 8; i++)
            #pragma unroll
            for (int j = 0; j < 8; j++) acc[i][j] = 0.0f;

        for (int kt = 0; kt < HD; kt += KT) {
            const float4* g  = (const float4*)(W1 + (size_t)kt * HD);
            float4* s4 = (float4*)Ws;
            #pragma unroll
            for (int s = 0; s < 8; s++) s4[tid + s * NT] = g[tid + s * NT];
            __syncthreads();

            #pragma unroll 2
            for (int k = 0; k < KT; k++) {
                float a[8], w[8];
                #pragma unroll
                for (int i = 0; i < 8; i++) a[i] = h0s[(ty * 8 + i) * HD + kt + k];
                #pragma unroll
                for (int j = 0; j < 8; j++) w[j] = Ws[k * HD + tx + j * 32];
                #pragma unroll
                for (int i = 0; i < 8; i++)
                    #pragma unroll
                    for (int j = 0; j < 8; j++)
                        acc[i][j] = fmaf(a[i], w[j], acc[i][j]);
            }
            __syncthreads();
        }

        #pragma unroll
        for (int j = 0; j < 8; j++) {
            const int c = tx + j * 32;
            const float bb = b1[c];
            #pragma unroll
            for (int i = 0; i < 8; i++)
                h1s[(ty * 8 + i) * HD + c] = fmaxf(acc[i][j] + bb, 0.0f);
        }
    }
    __syncthreads();

    // ---- stage 3: raw = h1 @ Wout + bout, 8x6 register tile (N padded 192) ----
    {
        float acc[8][6];
        #pragma unroll
        for (int i = 0; i < 8; i++)
            #pragma unroll
            for (int j = 0; j < 6; j++) acc[i][j] = 0.0f;

        for (int kt = 0; kt < HD; kt += KT) {
            #pragma unroll
            for (int s = 0; s < 24; s++) {   // 32*192 / 256
                int e = tid + s * NT;
                int k = e / OUTP, c = e - k * OUTP;
                Ws[e] = (c < OUTC) ? Wout[(size_t)(kt + k) * OUTC + c] : 0.0f;
            }
            __syncthreads();

            #pragma unroll 2
            for (int k = 0; k < KT; k++) {
                float a[8], w[6];
                #pragma unroll
                for (int i = 0; i < 8; i++) a[i] = h1s[(ty * 8 + i) * HD + kt + k];
                #pragma unroll
                for (int j = 0; j < 6; j++) w[j] = Ws[k * OUTP + tx + j * 32];
                #pragma unroll
                for (int i = 0; i < 8; i++)
                    #pragma unroll
                    for (int j = 0; j < 6; j++)
                        acc[i][j] = fmaf(a[i], w[j], acc[i][j]);
            }
            __syncthreads();
        }

        // write raw (+bout) into h0s region, stride OUTP
        #pragma unroll
        for (int j = 0; j < 6; j++) {
            const int c = tx + j * 32;
            if (c < OUTC) {
                const float bb = bout[c];
                #pragma unroll
                for (int i = 0; i < 8; i++)
                    h0s[(ty * 8 + i) * OUTP + c] = acc[i][j] + bb;
            }
        }
    }
    __syncthreads();

    // ---- stage 4: rational-quadratic spline per (row, transform) ----
    const float CNST = logf(expf(1.0f - 1e-4f) - 1.0f);
    #pragma unroll
    for (int p = 0; p < 2; p++) {
        const int task = tid + p * NT;          // 0..511
        const int r = task & (RB - 1);
        const int t = task >> 6;                // 0..7
        const float* raw = h0s + r * OUTP + t * 23;

        const float xv = x[(size_t)(row0 + r) * 16 + t];

        float rw[8], rh[8];
        #pragma unroll
        for (int c = 0; c < 8; c++) { rw[c] = raw[c]; rh[c] = raw[8 + c]; }

        // softmax(widths)
        float m = rw[0];
        #pragma unroll
        for (int c = 1; c < 8; c++) m = fmaxf(m, rw[c]);
        float sum = 0.0f, ew[8];
        #pragma unroll
        for (int c = 0; c < 8; c++) { ew[c] = expf(rw[c] - m); sum += ew[c]; }
        float inv = 1.0f / sum;
        float wdt[8];
        #pragma unroll
        for (int c = 0; c < 8; c++)
            wdt[c] = 2.0f * (1e-4f + (1.0f - 8e-4f) * ew[c] * inv);

        // softmax(heights)
        m = rh[0];
        #pragma unroll
        for (int c = 1; c < 8; c++) m = fmaxf(m, rh[c]);
        sum = 0.0f;
        #pragma unroll
        for (int c = 0; c < 8; c++) { ew[c] = expf(rh[c] - m); sum += ew[c]; }
        inv = 1.0f / sum;
        float hgt[8];
        #pragma unroll
        for (int c = 0; c < 8; c++)
            hgt[c] = 2.0f * (1e-4f + (1.0f - 8e-4f) * ew[c] * inv);

        // derivatives (padded with 1.0 at both ends)
        float dv[9];
        dv[0] = 1.0f; dv[8] = 1.0f;
        #pragma unroll
        for (int c = 0; c < 7; c++)
            dv[c + 1] = softplusf(raw[16 + c] + CNST) + 1e-4f;

        const bool mask = (xv <= -0.999f) || (xv >= 0.999f);
        const float xin = mask ? 0.0f : xv;

        // bin search via monotone predicated capture (== sum(edge<=x)-1, clipped)
        float cx = -1.0f, cy = -1.0f;
        float xk = -1.0f, yk = -1.0f, wk = wdt[0], hk = hgt[0], dk = dv[0], dk1 = dv[1];
        #pragma unroll
        for (int i = 0; i < 8; i++) {
            if (cx <= xin) {
                xk = cx; yk = cy; wk = wdt[i]; hk = hgt[i];
                dk = dv[i]; dk1 = dv[i + 1];
            }
            cx += wdt[i]; cy += hgt[i];
        }

        const float sk   = hk / wk;
        const float eps  = (xin - xk) / wk;
        const float et   = eps * (1.0f - eps);
        const float e2   = eps * eps;
        const float beta = sk + (dk1 + dk - 2.0f * sk) * et;
        const float alp  = hk * (sk * e2 + dk * et);
        const float y    = mask ? xv : (yk + alp / beta);
        const float ome  = 1.0f - eps;
        float ld = 2.0f * logf(sk)
                 + logf(dk1 * e2 + 2.0f * sk * et + dk * ome * ome)
                 - 2.0f * logf(beta);
        ld = mask ? 0.0f : ld;

        out[(size_t)(row0 + r) * 16 + t] = y;
        atomicAdd(&lds[r], ld);
    }

    // x2 passthrough
    for (int e = tid; e < RB * 8; e += NT) {
        int r = e >> 3, j = e & 7;
        out[(size_t)(row0 + r) * 16 + 8 + j] = x2s[e];
    }
    __syncthreads();

    if (tid < RB)
        out[(size_t)B * 16 + row0 + tid] = lds[tid];
}

extern "C" void kernel_launch(void* const* d_in, const int* in_sizes, int n_in,
                              void* d_out, int out_size) {
    const float* x    = (const float*)d_in[0];
    const float* W0   = (const float*)d_in[1];
    const float* b0   = (const float*)d_in[2];
    const float* W1   = (const float*)d_in[3];
    const float* b1   = (const float*)d_in[4];
    const float* Wout = (const float*)d_in[5];
    const float* bout = (const float*)d_in[6];
    float* out = (float*)d_out;

    const int B = in_sizes[0] / 16;
    const size_t smem_bytes = SMEM_FLOATS * sizeof(float);

    cudaFuncSetAttribute(coupling_spline_kernel,
                         cudaFuncAttributeMaxDynamicSharedMemorySize,
                         (int)smem_bytes);

    coupling_spline_kernel<<<B / RB, NT, smem_bytes>>>(
        x, W0, b0, W1, b1, Wout, bout, out, B);
}

// round 3
// speedup vs baseline: 3.5914x; 3.5914x over previous
#include <cuda_runtime.h>
#include <cuda_bf16.h>
#include <math.h>
#include <stdint.h>

#define NT    256
#define RB    128
#define AST   264            // A tile k-stride (bf16 units): 256 + 8 pad
#define WST   40             // W panel k-stride (bf16 units): 32 + 8 pad
#define A0ST  24
#define RSTR  193

// ---- smem layout (bytes) ----
#define OFF_AHI 0
#define OFF_ALO 67584                  // 128*264*2
#define OFF_WP  135168                 // 4 slots * 20480
#define SLOT_B  20480
#define OFF_B1S 217088                 // 256 f32
#define OFF_BOS 218112                 // 192 f32
#define OFF_B0S 218880                 // 256 f32
#define SMEM_BYTES 219904
// GEMM0 operands live inside WP region before the pipeline starts:
#define OFF_A0  (OFF_WP)               // 128*24*2 = 6144
#define OFF_B0A (OFF_WP + 8192)        // 256*24*2 = 12288
#define OFF_B0B (OFF_WP + 8192 + 12288)

#define PAN1_B 20480                   // 256*40*2
#define PAN2_B 15360                   // 192*40*2

// ---- prebuilt weight panel images ----
__device__ __align__(16) __nv_bfloat16 g_w1hi[8 * 256 * 40];
__device__ __align__(16) __nv_bfloat16 g_w1lo[8 * 256 * 40];
__device__ __align__(16) __nv_bfloat16 g_wohi[8 * 192 * 40];
__device__ __align__(16) __nv_bfloat16 g_wolo[8 * 192 * 40];
__device__ __align__(16) __nv_bfloat16 g_w0a[256 * 24];
__device__ __align__(16) __nv_bfloat16 g_w0b[256 * 24];

// ---- helpers ----
__device__ __forceinline__ uint32_t smem_u32(const void* p) {
    uint32_t a;
    asm("{ .reg .u64 t; cvta.to.shared.u64 t, %1; cvt.u32.u64 %0, t; }" : "=r"(a) : "l"(p));
    return a;
}
__device__ __forceinline__ void cp16(uint32_t dst, const void* src) {
    asm volatile("cp.async.cg.shared.global [%0], [%1], 16;" :: "r"(dst), "l"(src));
}
#define CP_COMMIT() asm volatile("cp.async.commit_group;")
#define CP_WAIT0()  asm volatile("cp.async.wait_group 0;")

__device__ __forceinline__ void mma16(float* d, uint32_t a0, uint32_t a1, uint32_t a2, uint32_t a3,
                                      uint32_t b0, uint32_t b1) {
    asm volatile("mma.sync.aligned.m16n8k16.row.col.f32.bf16.bf16.f32 "
                 "{%0,%1,%2,%3}, {%4,%5,%6,%7}, {%8,%9}, {%0,%1,%2,%3};"
                 : "+f"(d[0]), "+f"(d[1]), "+f"(d[2]), "+f"(d[3])
                 : "r"(a0), "r"(a1), "r"(a2), "r"(a3), "r"(b0), "r"(b1));
}

__device__ __forceinline__ float softplusf(float v) {
    return fmaxf(v, 0.0f) + log1pf(expf(-fabsf(v)));
}
__device__ __forceinline__ void split_bf16(float v, __nv_bfloat16& h, __nv_bfloat16& l) {
    h = __float2bfloat16(v);
    l = __float2bfloat16(v - __bfloat162float(h));
}

// 3-product k-panel compute: d += Ahi*Whi + Alo*Whi + Ahi*Wlo over 32 k
template<int NTILES>
__device__ __forceinline__ void panel_compute(const char* sm, const char* wb_hi, const char* wb_lo,
                                              int akbase, int nbase, int mw, int qr, int qc,
                                              float d[4][8][4])
{
    #pragma unroll
    for (int prod = 0; prod < 3; prod++) {
        const char* A = sm + ((prod == 1) ? OFF_ALO : OFF_AHI);
        const char* W = (prod == 2) ? wb_lo : wb_hi;
        #pragma unroll
        for (int ks = 0; ks < 2; ks++) {
            const int kA = akbase + ks * 16 + qc;
            const int kW = ks * 16 + qc;
            uint32_t a[4][4];
            #pragma unroll
            for (int mt = 0; mt < 4; mt++) {
                const uint32_t* ap = (const uint32_t*)(A + ((mw * 64 + mt * 16 + qr) * AST + kA) * 2);
                a[mt][0] = ap[0];
                a[mt][1] = ap[(8 * AST) / 2];
                a[mt][2] = ap[4];
                a[mt][3] = ap[(8 * AST) / 2 + 4];
            }
            #pragma unroll
            for (int nt = 0; nt < NTILES; nt++) {
                const uint32_t* bp = (const uint32_t*)(W + ((nbase + nt * 8 + qr) * WST + kW) * 2);
                uint32_t b0 = bp[0], b1 = bp[4];
                #pragma unroll
                for (int mt = 0; mt < 4; mt++)
                    mma16(d[mt][nt], a[mt][0], a[mt][1], a[mt][2], a[mt][3], b0, b1);
            }
        }
    }
}

// ---- prep kernels ----
__global__ void prep_w1(const float* __restrict__ W1) {
    int idx = blockIdx.x * blockDim.x + threadIdx.x;      // 81920
    int p = idx / 10240, rem = idx % 10240;
    int n = rem / 40, kk = rem % 40;
    float w = (kk < 32) ? W1[(p * 32 + kk) * 256 + n] : 0.0f;
    __nv_bfloat16 h, l; split_bf16(w, h, l);
    g_w1hi[idx] = h; g_w1lo[idx] = l;
}
__global__ void prep_wo(const float* __restrict__ Wout) {
    int idx = blockIdx.x * blockDim.x + threadIdx.x;      // 61440
    int p = idx / 7680, rem = idx % 7680;
    int n = rem / 40, kk = rem % 40;
    float w = (kk < 32 && n < 184) ? Wout[(p * 32 + kk) * 184 + n] : 0.0f;
    __nv_bfloat16 h, l; split_bf16(w, h, l);
    g_wohi[idx] = h; g_wolo[idx] = l;
}
__global__ void prep_w0(const float* __restrict__ W0) {
    int idx = blockIdx.x * blockDim.x + threadIdx.x;      // 6144
    int n = idx / 24, j = idx % 24;
    float w = (j < 16) ? W0[(j & 7) * 256 + n] : 0.0f;
    __nv_bfloat16 h, l; split_bf16(w, h, l);
    g_w0a[idx] = h;                              // [Whi ; Whi ; 0]
    g_w0b[idx] = (j < 8) ? l : __float2bfloat16(0.0f);  // [Wlo ; 0 ; 0]
}

// ---- main kernel ----
__global__ void __launch_bounds__(NT, 1)
coupling_hmma_kernel(const float* __restrict__ x,
                     const float* __restrict__ b0,
                     const float* __restrict__ b1,
                     const float* __restrict__ bout,
                     float* __restrict__ out,
                     int B)
{
    extern __shared__ char sm[];
    const int tid = threadIdx.x;
    const int wid = tid >> 5, lane = tid & 31;
    const int mw = wid & 1, nw = wid >> 1;
    const int qr = lane >> 2, qc = (lane & 3) * 2;
    const int row0 = blockIdx.x * RB;

    float* b0s = (float*)(sm + OFF_B0S);
    float* b1s = (float*)(sm + OFF_B1S);
    float* bos = (float*)(sm + OFF_BOS);

    // ---- prologue: biases, GEMM0 operands ----
    for (int i = tid; i < 256; i += NT) { b0s[i] = b0[i]; b1s[i] = b1[i]; }
    for (int i = tid; i < 192; i += NT) bos[i] = (i < 184) ? bout[i] : 0.0f;
    for (int i = tid; i < 768; i += NT) {
        ((uint4*)(sm + OFF_B0A))[i] = ((const uint4*)g_w0a)[i];
        ((uint4*)(sm + OFF_B0B))[i] = ((const uint4*)g_w0b)[i];
    }
    if (tid < RB) {
        const float4* xp = (const float4*)(x + (size_t)(row0 + tid) * 16);
        float4 xc = xp[2], xd = xp[3];
        float xv[8] = {xc.x, xc.y, xc.z, xc.w, xd.x, xd.y, xd.z, xd.w};
        __nv_bfloat162* a0 = (__nv_bfloat162*)(sm + OFF_A0 + tid * A0ST * 2);
        #pragma unroll
        for (int j = 0; j < 8; j += 2) {
            __nv_bfloat16 h0, l0, h1, l1;
            split_bf16(xv[j], h0, l0);
            split_bf16(xv[j + 1], h1, l1);
            a0[j / 2]     = __nv_bfloat162(h0, h1);   // k = j, j+1 (hi)
            a0[4 + j / 2] = __nv_bfloat162(l0, l1);   // k = 8+j   (lo)
            a0[8 + j / 2] = __nv_bfloat162(__float2bfloat16(0.f), __float2bfloat16(0.f));
        }
    }
    __syncthreads();

    float d[4][8][4];
    #pragma unroll
    for (int mt = 0; mt < 4; mt++)
        #pragma unroll
        for (int nt = 0; nt < 8; nt++)
            #pragma unroll
            for (int i = 0; i < 4; i++) d[mt][nt][i] = 0.0f;

    // ---- GEMM0: h0 = x2 @ W0  (2 passes of K=16) ----
    #pragma unroll
    for (int pass = 0; pass < 2; pass++) {
        const char* W = sm + (pass ? OFF_B0B : OFF_B0A);
        uint32_t a[4][4];
        #pragma unroll
        for (int mt = 0; mt < 4; mt++) {
            const uint32_t* ap = (const uint32_t*)(sm + OFF_A0 + ((mw * 64 + mt * 16 + qr) * A0ST + qc) * 2);
            a[mt][0] = ap[0];
            a[mt][1] = ap[(8 * A0ST) / 2];
            a[mt][2] = ap[4];
            a[mt][3] = ap[(8 * A0ST) / 2 + 4];
        }
        #pragma unroll
        for (int nt = 0; nt < 8; nt++) {
            const uint32_t* bp = (const uint32_t*)(W + ((nw * 64 + nt * 8 + qr) * A0ST + qc) * 2);
            uint32_t bb0 = bp[0], bb1 = bp[4];
            #pragma unroll
            for (int mt = 0; mt < 4; mt++)
                mma16(d[mt][nt], a[mt][0], a[mt][1], a[mt][2], a[mt][3], bb0, bb1);
        }
    }
    __syncthreads();   // all GEMM0 reads of A0/B0 done -> WP region free

    // ---- epilogue0: h0 = relu(d + b0) -> Ahi/Alo ----
    #pragma unroll
    for (int mt = 0; mt < 4; mt++) {
        const int r0 = mw * 64 + mt * 16 + qr;
        #pragma unroll
        for (int nt = 0; nt < 8; nt++) {
            const int c = nw * 64 + nt * 8 + qc;
            const float g0 = b0s[c], g1 = b0s[c + 1];
            float v00 = fmaxf(d[mt][nt][0] + g0, 0.f), v01 = fmaxf(d[mt][nt][1] + g1, 0.f);
            float v10 = fmaxf(d[mt][nt][2] + g0, 0.f), v11 = fmaxf(d[mt][nt][3] + g1, 0.f);
            __nv_bfloat16 h, l, h2, l2;
            split_bf16(v00, h, l); split_bf16(v01, h2, l2);
            *(__nv_bfloat162*)(sm + OFF_AHI + (r0 * AST + c) * 2) = __nv_bfloat162(h, h2);
            *(__nv_bfloat162*)(sm + OFF_ALO + (r0 * AST + c) * 2) = __nv_bfloat162(l, l2);
            split_bf16(v10, h, l); split_bf16(v11, h2, l2);
            *(__nv_bfloat162*)(sm + OFF_AHI + ((r0 + 8) * AST + c) * 2) = __nv_bfloat162(h, h2);
            *(__nv_bfloat162*)(sm + OFF_ALO + ((r0 + 8) * AST + c) * 2) = __nv_bfloat162(l, l2);
            #pragma unroll
            for (int i = 0; i < 4; i++) d[mt][nt][i] = 0.0f;
        }
    }
    __syncthreads();   // Ahi/Alo visible to all; WP safe to overwrite

    // ---- panel pipeline: p 0..7 = GEMM1 (W1), p 8..15 = GEMM2 (Wout) ----
    const uint32_t wp_u32 = smem_u32(sm + OFF_WP);

    // issue(0)
    {
        const char* shi = (const char*)g_w1hi;
        const char* slo = (const char*)g_w1lo;
        uint32_t dhi = wp_u32, dlo = wp_u32 + SLOT_B;
        for (int i = tid; i < PAN1_B / 16; i += NT) {
            cp16(dhi + i * 16, shi + i * 16);
            cp16(dlo + i * 16, slo + i * 16);
        }
        CP_COMMIT();
    }

    for (int p = 0; p < 16; p++) {
        CP_WAIT0();
        __syncthreads();

        if (p == 8) {
            // epilogue1: h1 = relu(d + b1) -> Ahi/Alo (GEMM1 reads all done via barrier)
            #pragma unroll
            for (int mt = 0; mt < 4; mt++) {
                const int r0 = mw * 64 + mt * 16 + qr;
                #pragma unroll
                for (int nt = 0; nt < 8; nt++) {
                    const int c = nw * 64 + nt * 8 + qc;
                    const float g0 = b1s[c], g1 = b1s[c + 1];
                    float v00 = fmaxf(d[mt][nt][0] + g0, 0.f), v01 = fmaxf(d[mt][nt][1] + g1, 0.f);
                    float v10 = fmaxf(d[mt][nt][2] + g0, 0.f), v11 = fmaxf(d[mt][nt][3] + g1, 0.f);
                    __nv_bfloat16 h, l, h2, l2;
                    split_bf16(v00, h, l); split_bf16(v01, h2, l2);
                    *(__nv_bfloat162*)(sm + OFF_AHI + (r0 * AST + c) * 2) = __nv_bfloat162(h, h2);
                    *(__nv_bfloat162*)(sm + OFF_ALO + (r0 * AST + c) * 2) = __nv_bfloat162(l, l2);
                    split_bf16(v10, h, l); split_bf16(v11, h2, l2);
                    *(__nv_bfloat162*)(sm + OFF_AHI + ((r0 + 8) * AST + c) * 2) = __nv_bfloat162(h, h2);
                    *(__nv_bfloat162*)(sm + OFF_ALO + ((r0 + 8) * AST + c) * 2) = __nv_bfloat162(l, l2);
                    #pragma unroll
                    for (int i = 0; i < 4; i++) d[mt][nt][i] = 0.0f;
                }
            }
            __syncthreads();
        }

        if (p + 1 < 16) {    // issue(p+1) into other stage (prev contents fully consumed)
            const int np = p + 1;
            const int stage = np & 1;
            uint32_t dhi = wp_u32 + stage * 2 * SLOT_B;
            uint32_t dlo = dhi + SLOT_B;
            if (np < 8) {
                const char* shi = (const char*)g_w1hi + np * PAN1_B;
                const char* slo = (const char*)g_w1lo + np * PAN1_B;
                for (int i = tid; i < PAN1_B / 16; i += NT) {
                    cp16(dhi + i * 16, shi + i * 16);
                    cp16(dlo + i * 16, slo + i * 16);
                }
            } else {
                const char* shi = (const char*)g_wohi + (np - 8) * PAN2_B;
                const char* slo = (const char*)g_wolo + (np - 8) * PAN2_B;
                for (int i = tid; i < PAN2_B / 16; i += NT) {
                    cp16(dhi + i * 16, shi + i * 16);
                    cp16(dlo + i * 16, slo + i * 16);
                }
            }
            CP_COMMIT();
        } else {
            CP_COMMIT();     // keep wait_group bookkeeping uniform
        }

        const int stage = p & 1;
        const char* wb_hi = sm + OFF_WP + stage * 2 * SLOT_B;
        const char* wb_lo = wb_hi + SLOT_B;
        if (p < 8)
            panel_compute<8>(sm, wb_hi, wb_lo, p * 32, nw * 64, mw, qr, qc, d);
        else
            panel_compute<6>(sm, wb_hi, wb_lo, (p - 8) * 32, nw * 48, mw, qr, qc, d);
    }
    __syncthreads();   // all GEMM2 reads of Ahi/Alo done

    // ---- epilogue2: raw = d + bout -> smem f32 [128][193] (overlaps A region) ----
    float* rawS = (float*)(sm + OFF_AHI);
    #pragma unroll
    for (int mt = 0; mt < 4; mt++) {
        const int r0 = mw * 64 + mt * 16 + qr;
        #pragma unroll
        for (int nt = 0; nt < 6; nt++) {
            const int c = nw * 48 + nt * 8 + qc;
            rawS[r0 * RSTR + c]           = d[mt][nt][0] + bos[c];
            rawS[r0 * RSTR + c + 1]       = d[mt][nt][1] + bos[c + 1];
            rawS[(r0 + 8) * RSTR + c]     = d[mt][nt][2] + bos[c];
            rawS[(r0 + 8) * RSTR + c + 1] = d[mt][nt][3] + bos[c + 1];
        }
    }
    __syncthreads();

    // ---- spline: thread -> (row = tid/2, 4 transforms) ----
    {
        const int r = tid >> 1;
        const int ts = (tid & 1) * 4;
        const size_t grow = (size_t)(row0 + r) * 16;
        const float4 x1q = *(const float4*)(x + grow + ts);
        const float x1v[4] = {x1q.x, x1q.y, x1q.z, x1q.w};
        const float CNST = logf(expf(1.0f - 1e-4f) - 1.0f);
        float yv[4];
        float ldsum = 0.0f;

        #pragma unroll 1
        for (int tt = 0; tt < 4; tt++) {
            const float* raw = rawS + r * RSTR + (ts + tt) * 23;
            const float xv = x1v[tt];

            float rw[8], rh[8];
            #pragma unroll
            for (int c = 0; c < 8; c++) { rw[c] = raw[c]; rh[c] = raw[8 + c]; }

            float m = rw[0];
            #pragma unroll
            for (int c = 1; c < 8; c++) m = fmaxf(m, rw[c]);
            float sum = 0.0f, ew[8];
            #pragma unroll
            for (int c = 0; c < 8; c++) { ew[c] = expf(rw[c] - m); sum += ew[c]; }
            float inv = 1.0f / sum;
            float wdt[8];
            #pragma unroll
            for (int c = 0; c < 8; c++) wdt[c] = 2.0f * (1e-4f + (1.0f - 8e-4f) * ew[c] * inv);

            m = rh[0];
            #pragma unroll
            for (int c = 1; c < 8; c++) m = fmaxf(m, rh[c]);
            sum = 0.0f;
            #pragma unroll
            for (int c = 0; c < 8; c++) { ew[c] = expf(rh[c] - m); sum += ew[c]; }
            inv = 1.0f / sum;
            float hgt[8];
            #pragma unroll
            for (int c = 0; c < 8; c++) hgt[c] = 2.0f * (1e-4f + (1.0f - 8e-4f) * ew[c] * inv);

            float dv[9];
            dv[0] = 1.0f; dv[8] = 1.0f;
            #pragma unroll
            for (int c = 0; c < 7; c++) dv[c + 1] = softplusf(raw[16 + c] + CNST) + 1e-4f;

            const bool mask = (xv <= -0.999f) || (xv >= 0.999f);
            const float xin = mask ? 0.0f : xv;

            float cx = -1.0f, cy = -1.0f;
            float xk = -1.0f, yk = -1.0f, wk = wdt[0], hk = hgt[0], dk = dv[0], dk1 = dv[1];
            #pragma unroll
            for (int i = 0; i < 8; i++) {
                if (cx <= xin) { xk = cx; yk = cy; wk = wdt[i]; hk = hgt[i]; dk = dv[i]; dk1 = dv[i + 1]; }
                cx += wdt[i]; cy += hgt[i];
            }

            const float sk   = hk / wk;
            const float eps  = (xin - xk) / wk;
            const float et   = eps * (1.0f - eps);
            const float e2   = eps * eps;
            const float beta = sk + (dk1 + dk - 2.0f * sk) * et;
            const float alp  = hk * (sk * e2 + dk * et);
            yv[tt] = mask ? xv : (yk + alp / beta);
            const float ome = 1.0f - eps;
            float ld = 2.0f * logf(sk)
                     + logf(dk1 * e2 + 2.0f * sk * et + dk * ome * ome)
                     - 2.0f * logf(beta);
            ldsum += mask ? 0.0f : ld;
        }

        // outputs
        *(float4*)(out + grow + ts) = make_float4(yv[0], yv[1], yv[2], yv[3]);
        *(float4*)(out + grow + 8 + ts) = *(const float4*)(x + grow + 8 + ts);

        ldsum += __shfl_xor_sync(0xffffffffu, ldsum, 1);
        if ((tid & 1) == 0)
            out[(size_t)B * 16 + row0 + r] = ldsum;
    }
}

extern "C" void kernel_launch(void* const* d_in, const int* in_sizes, int n_in,
                              void* d_out, int out_size) {
    const float* x    = (const float*)d_in[0];
    const float* W0   = (const float*)d_in[1];
    const float* b0   = (const float*)d_in[2];
    const float* W1   = (const float*)d_in[3];
    const float* b1   = (const float*)d_in[4];
    const float* Wout = (const float*)d_in[5];
    const float* bout = (const float*)d_in[6];
    float* out = (float*)d_out;

    const int B = in_sizes[0] / 16;

    prep_w1<<<320, 256>>>(W1);
    prep_wo<<<240, 256>>>(Wout);
    prep_w0<<<24, 256>>>(W0);

    cudaFuncSetAttribute(coupling_hmma_kernel,
                         cudaFuncAttributeMaxDynamicSharedMemorySize, SMEM_BYTES);
    coupling_hmma_kernel<<<B / RB, NT, SMEM_BYTES>>>(x, b0, b1, bout, out, B);
}

// round 4
// speedup vs baseline: 4.4417x; 1.2368x over previous
#include <cuda_runtime.h>
#include <cuda_fp16.h>
#include <math.h>
#include <stdint.h>

#define NT    256
#define RB    128
#define AST   264            // A tile k-stride (fp16 units): 256 + 8 pad
#define WST   40             // W panel k-stride (fp16 units): 32 + 8 pad
#define RSTR  193
#define INV32 0.03125f

// ---- smem layout (bytes) ----
#define OFF_A       0                   // 128*264*2 = 67584 (fp16 hi only)
#define OFF_WP      67584               // 2 stages * 40960
#define SLOT_STRIDE 40960
#define LO_OFF      20480
#define OFF_W0S     149504              // 8*256 f32 = 8192
#define OFF_B1S     157696              // 256 f32
#define OFF_BOS     158720              // 192 f32
#define OFF_B0S     159488              // 256 f32
#define SMEM_BYTES  160512
// raw buffer (epilogue2) overlaps A+WP: 128*193*4 = 98816 <= 149504

// ---- prebuilt weight panel images (fp16, scaled x32, hi/lo split) ----
__device__ __align__(16) __half g_w1h[8 * 256 * 40];
__device__ __align__(16) __half g_w1l[8 * 256 * 40];
__device__ __align__(16) __half g_woh[8 * 192 * 40];
__device__ __align__(16) __half g_wol[8 * 192 * 40];

// ---- helpers ----
__device__ __forceinline__ uint32_t smem_u32(const void* p) {
    uint32_t a;
    asm("{ .reg .u64 t; cvta.to.shared.u64 t, %1; cvt.u32.u64 %0, t; }" : "=r"(a) : "l"(p));
    return a;
}
__device__ __forceinline__ void cp16(uint32_t dst, const void* src) {
    asm volatile("cp.async.cg.shared.global [%0], [%1], 16;" :: "r"(dst), "l"(src));
}
#define CP_COMMIT() asm volatile("cp.async.commit_group;")
#define CP_WAIT0()  asm volatile("cp.async.wait_group 0;")

__device__ __forceinline__ void mma16(float* d, uint32_t a0, uint32_t a1, uint32_t a2, uint32_t a3,
                                      uint32_t b0, uint32_t b1) {
    asm volatile("mma.sync.aligned.m16n8k16.row.col.f32.f16.f16.f32 "
                 "{%0,%1,%2,%3}, {%4,%5,%6,%7}, {%8,%9}, {%0,%1,%2,%3};"
                 : "+f"(d[0]), "+f"(d[1]), "+f"(d[2]), "+f"(d[3])
                 : "r"(a0), "r"(a1), "r"(a2), "r"(a3), "r"(b0), "r"(b1));
}

__device__ __forceinline__ float softplusf(float v) {
    return fmaxf(v, 0.0f) + log1pf(expf(-fabsf(v)));
}

// 2-product k-panel compute: d += A*(Whi) + A*(Wlo), A loaded once per k16
template<int NTILES>
__device__ __forceinline__ void panel_compute(const char* A, const char* Whi, const char* Wlo,
                                              int akbase, int nbase, int mrow, int qr, int qc,
                                              float d[4][8][4])
{
    #pragma unroll
    for (int ks = 0; ks < 2; ks++) {
        const int kA = akbase + ks * 16 + qc;
        const int kW = ks * 16 + qc;
        uint32_t a[4][4];
        #pragma unroll
        for (int mt = 0; mt < 4; mt++) {
            const uint32_t* ap = (const uint32_t*)(A + ((mrow + mt * 16 + qr) * AST + kA) * 2);
            a[mt][0] = ap[0];
            a[mt][1] = ap[4 * AST];          // +8 rows
            a[mt][2] = ap[4];                // +8 k
            a[mt][3] = ap[4 * AST + 4];
        }
        #pragma unroll
        for (int nt = 0; nt < NTILES; nt++) {
            const int woff = ((nbase + nt * 8 + qr) * WST + kW) * 2;
            const uint32_t* bh = (const uint32_t*)(Whi + woff);
            const uint32_t* bl = (const uint32_t*)(Wlo + woff);
            uint32_t h0 = bh[0], h1 = bh[4];
            uint32_t l0 = bl[0], l1 = bl[4];
            #pragma unroll
            for (int mt = 0; mt < 4; mt++) {
                mma16(d[mt][nt], a[mt][0], a[mt][1], a[mt][2], a[mt][3], h0, h1);
                mma16(d[mt][nt], a[mt][0], a[mt][1], a[mt][2], a[mt][3], l0, l1);
            }
        }
    }
}

// ---- prep kernels: fp16 hi/lo panels of 32*W ----
__global__ void prep_w1(const float* __restrict__ W1) {
    int idx = blockIdx.x * blockDim.x + threadIdx.x;      // 81920
    int p = idx / 10240, rem = idx % 10240;
    int n = rem / 40, kk = rem % 40;
    float w = (kk < 32) ? 32.0f * W1[(p * 32 + kk) * 256 + n] : 0.0f;
    __half h = __float2half_rn(w);
    __half l = __float2half_rn(w - __half2float(h));
    g_w1h[idx] = h; g_w1l[idx] = l;
}
__global__ void prep_wo(const float* __restrict__ Wout) {
    int idx = blockIdx.x * blockDim.x + threadIdx.x;      // 61440
    int p = idx / 7680, rem = idx % 7680;
    int n = rem / 40, kk = rem % 40;
    float w = (kk < 32 && n < 184) ? 32.0f * Wout[(p * 32 + kk) * 184 + n] : 0.0f;
    __half h = __float2half_rn(w);
    __half l = __float2half_rn(w - __half2float(h));
    g_woh[idx] = h; g_wol[idx] = l;
}

// ---- main kernel ----
__global__ void __launch_bounds__(NT, 1)
coupling_hmma_kernel(const float* __restrict__ x,
                     const float* __restrict__ W0,
                     const float* __restrict__ b0,
                     const float* __restrict__ b1,
                     const float* __restrict__ bout,
                     float* __restrict__ out,
                     int B)
{
    extern __shared__ char sm[];
    const int tid = threadIdx.x;
    const int wid = tid >> 5, lane = tid & 31;
    const int mw = wid & 1, nw = wid >> 1;
    const int qr = lane >> 2, qc = (lane & 3) * 2;
    const int row0 = blockIdx.x * RB;
    const uint32_t wp_u32 = smem_u32(sm + OFF_WP);

    float* b0s = (float*)(sm + OFF_B0S);
    float* b1s = (float*)(sm + OFF_B1S);
    float* bos = (float*)(sm + OFF_BOS);
    float* W0s = (float*)(sm + OFF_W0S);

    // ---- prefetch first W1 panel immediately (overlaps GEMM0) ----
    {
        const char* shi = (const char*)g_w1h;
        const char* slo = (const char*)g_w1l;
        uint32_t dhi = wp_u32, dlo = wp_u32 + LO_OFF;
        for (int i = tid; i < 1280; i += NT) {
            cp16(dhi + i * 16, shi + i * 16);
            cp16(dlo + i * 16, slo + i * 16);
        }
        CP_COMMIT();
    }

    // ---- prologue constants ----
    for (int i = tid; i < 256; i += NT) { b0s[i] = b0[i]; b1s[i] = b1[i]; }
    for (int i = tid; i < 192; i += NT) bos[i] = (i < 184) ? bout[i] : 0.0f;
    for (int i = tid; i < 2048; i += NT) W0s[i] = W0[i];
    __syncthreads();

    // ---- GEMM0 (exact fp32 FFMA): h0 = relu(x2 @ W0 + b0) -> fp16 A tile ----
    {
        const int r = tid & 127, half = tid >> 7;
        const int cb = half * 128;
        const float4* xp = (const float4*)(x + (size_t)(row0 + r) * 16);
        float4 xc = xp[2], xd = xp[3];
        float xv[8] = {xc.x, xc.y, xc.z, xc.w, xd.x, xd.y, xd.z, xd.w};
        for (int c = 0; c < 128; c += 2) {
            float s0 = b0s[cb + c], s1 = b0s[cb + c + 1];
            #pragma unroll
            for (int j = 0; j < 8; j++) {
                s0 = fmaf(xv[j], W0s[j * 256 + cb + c], s0);
                s1 = fmaf(xv[j], W0s[j * 256 + cb + c + 1], s1);
            }
            s0 = fmaxf(s0, 0.0f); s1 = fmaxf(s1, 0.0f);
            __half2 hv = __floats2half2_rn(s0, s1);
            *(__half2*)(sm + OFF_A + ((size_t)r * AST + cb + c) * 2) = hv;
        }
    }
    __syncthreads();

    float d[4][8][4];
    #pragma unroll
    for (int mt = 0; mt < 4; mt++)
        #pragma unroll
        for (int nt = 0; nt < 8; nt++)
            #pragma unroll
            for (int i = 0; i < 4; i++) d[mt][nt][i] = 0.0f;

    // ---- panel pipeline: p 0..7 = GEMM1 (W1), p 8..15 = GEMM2 (Wout) ----
    for (int p = 0; p < 16; p++) {
        CP_WAIT0();
        __syncthreads();

        if (p == 8) {
            // epilogue1: h1 = relu(d/32 + b1) -> fp16 A tile
            #pragma unroll
            for (int mt = 0; mt < 4; mt++) {
                const int r0 = mw * 64 + mt * 16 + qr;
                #pragma unroll
                for (int nt = 0; nt < 8; nt++) {
                    const int c = nw * 64 + nt * 8 + qc;
                    const float g0 = b1s[c], g1 = b1s[c + 1];
                    float v00 = fmaxf(fmaf(d[mt][nt][0], INV32, g0), 0.f);
                    float v01 = fmaxf(fmaf(d[mt][nt][1], INV32, g1), 0.f);
                    float v10 = fmaxf(fmaf(d[mt][nt][2], INV32, g0), 0.f);
                    float v11 = fmaxf(fmaf(d[mt][nt][3], INV32, g1), 0.f);
                    *(__half2*)(sm + OFF_A + ((size_t)r0 * AST + c) * 2) = __floats2half2_rn(v00, v01);
                    *(__half2*)(sm + OFF_A + ((size_t)(r0 + 8) * AST + c) * 2) = __floats2half2_rn(v10, v11);
                    #pragma unroll
                    for (int i = 0; i < 4; i++) d[mt][nt][i] = 0.0f;
                }
            }
            __syncthreads();
        }

        // issue(p+1) into the other stage (its previous contents consumed last iter)
        if (p + 1 < 16) {
            const int np = p + 1;
            const int stage = np & 1;
            uint32_t dhi = wp_u32 + stage * SLOT_STRIDE;
            uint32_t dlo = dhi + LO_OFF;
            if (np < 8) {
                const char* shi = (const char*)g_w1h + (size_t)np * 20480;
                const char* slo = (const char*)g_w1l + (size_t)np * 20480;
                for (int i = tid; i < 1280; i += NT) {
                    cp16(dhi + i * 16, shi + i * 16);
                    cp16(dlo + i * 16, slo + i * 16);
                }
            } else {
                const char* shi = (const char*)g_woh + (size_t)(np - 8) * 15360;
                const char* slo = (const char*)g_wol + (size_t)(np - 8) * 15360;
                for (int i = tid; i < 960; i += NT) {
                    cp16(dhi + i * 16, shi + i * 16);
                    cp16(dlo + i * 16, slo + i * 16);
                }
            }
            CP_COMMIT();
        } else {
            CP_COMMIT();
        }

        const int stage = p & 1;
        const char* wb = sm + OFF_WP + stage * SLOT_STRIDE;
        if (p < 8)
            panel_compute<8>(sm + OFF_A, wb, wb + LO_OFF, p * 32, nw * 64, mw * 64, qr, qc, d);
        else
            panel_compute<6>(sm + OFF_A, wb, wb + LO_OFF, (p - 8) * 32, nw * 48, mw * 64, qr, qc, d);
    }
    __syncthreads();   // all GEMM2 A reads done

    // ---- epilogue2: raw = d/32 + bout -> smem f32 [128][193] (overlaps A+WP) ----
    float* rawS = (float*)sm;
    #pragma unroll
    for (int mt = 0; mt < 4; mt++) {
        const int r0 = mw * 64 + mt * 16 + qr;
        #pragma unroll
        for (int nt = 0; nt < 6; nt++) {
            const int c = nw * 48 + nt * 8 + qc;
            rawS[r0 * RSTR + c]           = fmaf(d[mt][nt][0], INV32, bos[c]);
            rawS[r0 * RSTR + c + 1]       = fmaf(d[mt][nt][1], INV32, bos[c + 1]);
            rawS[(r0 + 8) * RSTR + c]     = fmaf(d[mt][nt][2], INV32, bos[c]);
            rawS[(r0 + 8) * RSTR + c + 1] = fmaf(d[mt][nt][3], INV32, bos[c + 1]);
        }
    }
    __syncthreads();

    // ---- spline: thread -> (row = tid/2, 4 transforms) ----
    {
        const int r = tid >> 1;
        const int ts = (tid & 1) * 4;
        const size_t grow = (size_t)(row0 + r) * 16;
        const float4 x1q = *(const float4*)(x + grow + ts);
        const float x1v[4] = {x1q.x, x1q.y, x1q.z, x1q.w};
        const float CNST = logf(expf(1.0f - 1e-4f) - 1.0f);
        float yv[4];
        float ldsum = 0.0f;

        #pragma unroll 1
        for (int tt = 0; tt < 4; tt++) {
            const float* raw = rawS + r * RSTR + (ts + tt) * 23;
            const float xv = x1v[tt];

            float rw[8], rh[8];
            #pragma unroll
            for (int c = 0; c < 8; c++) { rw[c] = raw[c]; rh[c] = raw[8 + c]; }

            float m = rw[0];
            #pragma unroll
            for (int c = 1; c < 8; c++) m = fmaxf(m, rw[c]);
            float sum = 0.0f, ew[8];
            #pragma unroll
            for (int c = 0; c < 8; c++) { ew[c] = expf(rw[c] - m); sum += ew[c]; }
            float inv = 1.0f / sum;
            float wdt[8];
            #pragma unroll
            for (int c = 0; c < 8; c++) wdt[c] = 2.0f * (1e-4f + (1.0f - 8e-4f) * ew[c] * inv);

            m = rh[0];
            #pragma unroll
            for (int c = 1; c < 8; c++) m = fmaxf(m, rh[c]);
            sum = 0.0f;
            #pragma unroll
            for (int c = 0; c < 8; c++) { ew[c] = expf(rh[c] - m); sum += ew[c]; }
            inv = 1.0f / sum;
            float hgt[8];
            #pragma unroll
            for (int c = 0; c < 8; c++) hgt[c] = 2.0f * (1e-4f + (1.0f - 8e-4f) * ew[c] * inv);

            float dv[9];
            dv[0] = 1.0f; dv[8] = 1.0f;
            #pragma unroll
            for (int c = 0; c < 7; c++) dv[c + 1] = softplusf(raw[16 + c] + CNST) + 1e-4f;

            const bool mask = (xv <= -0.999f) || (xv >= 0.999f);
            const float xin = mask ? 0.0f : xv;

            float cx = -1.0f, cy = -1.0f;
            float xk = -1.0f, yk = -1.0f, wk = wdt[0], hk = hgt[0], dk = dv[0], dk1 = dv[1];
            #pragma unroll
            for (int i = 0; i < 8; i++) {
                if (cx <= xin) { xk = cx; yk = cy; wk = wdt[i]; hk = hgt[i]; dk = dv[i]; dk1 = dv[i + 1]; }
                cx += wdt[i]; cy += hgt[i];
            }

            const float sk   = hk / wk;
            const float eps  = (xin - xk) / wk;
            const float et   = eps * (1.0f - eps);
            const float e2   = eps * eps;
            const float beta = sk + (dk1 + dk - 2.0f * sk) * et;
            const float alp  = hk * (sk * e2 + dk * et);
            yv[tt] = mask ? xv : (yk + alp / beta);
            const float ome = 1.0f - eps;
            float ld = 2.0f * logf(sk)
                     + logf(dk1 * e2 + 2.0f * sk * et + dk * ome * ome)
                     - 2.0f * logf(beta);
            ldsum += mask ? 0.0f : ld;
        }

        // outputs
        *(float4*)(out + grow + ts) = make_float4(yv[0], yv[1], yv[2], yv[3]);
        *(float4*)(out + grow + 8 + ts) = *(const float4*)(x + grow + 8 + ts);

        ldsum += __shfl_xor_sync(0xffffffffu, ldsum, 1);
        if ((tid & 1) == 0)
            out[(size_t)B * 16 + row0 + r] = ldsum;
    }
}

extern "C" void kernel_launch(void* const* d_in, const int* in_sizes, int n_in,
                              void* d_out, int out_size) {
    const float* x    = (const float*)d_in[0];
    const float* W0   = (const float*)d_in[1];
    const float* b0   = (const float*)d_in[2];
    const float* W1   = (const float*)d_in[3];
    const float* b1   = (const float*)d_in[4];
    const float* Wout = (const float*)d_in[5];
    const float* bout = (const float*)d_in[6];
    float* out = (float*)d_out;

    const int B = in_sizes[0] / 16;

    prep_w1<<<320, 256>>>(W1);
    prep_wo<<<240, 256>>>(Wout);

    cudaFuncSetAttribute(coupling_hmma_kernel,
                         cudaFuncAttributeMaxDynamicSharedMemorySize, SMEM_BYTES);
    coupling_hmma_kernel<<<B / RB, NT, SMEM_BYTES>>>(x, W0, b0, b1, bout, out, B);
}